// round 5
// baseline (speedup 1.0000x reference)
#include <cuda_runtime.h>
#include <cstddef>

#define B_ 2
#define C_ 256
#define N_ 4096
#define CN (C_*N_)

// ---------------- scratch (static __device__, no allocation) ----------------
__device__ float g_hn[B_*CN];        // groupnorm output (b, c, n)
__device__ float g_wT[4*C_*C_];      // wq^T, wk^T, wv^T, wp^T  (c, o)
__device__ float g_q [B_*CN];        // q (b, c, n)
__device__ float g_k [B_*CN];        // k (b, c, n)
__device__ float g_vT[B_*CN];        // v transposed (b, n, c)
__device__ float g_hv[B_*CN];        // hv (b, c, n)
__device__ float g_partial[B_*N_*32];// per (b,i,mtile) partial exp-sums
__device__ float g_rinv[B_*N_];      // 1/rowsum

// ---------------- packed f32x2 helpers ----------------
__device__ __forceinline__ unsigned long long pk2(float lo, float hi){
    unsigned long long r;
    asm("mov.b64 %0,{%1,%2};" : "=l"(r) : "f"(lo), "f"(hi));
    return r;
}
__device__ __forceinline__ float2 upk2(unsigned long long v){
    float2 f;
    asm("mov.b64 {%0,%1},%2;" : "=f"(f.x), "=f"(f.y) : "l"(v));
    return f;
}
__device__ __forceinline__ void fma2(unsigned long long& d, unsigned long long a, unsigned long long b){
    asm("fma.rn.f32x2 %0,%1,%2,%0;" : "+l"(d) : "l"(a), "l"(b));
}

// ---------------- weight transpose: wT[c][o] = W[o][c] ----------------
__global__ void transpose4(const float* __restrict__ wq, const float* __restrict__ wk,
                           const float* __restrict__ wv, const float* __restrict__ wp,
                           float* __restrict__ wT){
    __shared__ float t[32][33];
    const float* src = (blockIdx.z==0)?wq:(blockIdx.z==1)?wk:(blockIdx.z==2)?wv:wp;
    float* dst = wT + (size_t)blockIdx.z*C_*C_;
    int x0 = blockIdx.x*32, y0 = blockIdx.y*32;
    int tx = threadIdx.x, ty = threadIdx.y;
    #pragma unroll
    for (int r=0;r<32;r+=8) t[ty+r][tx] = src[(size_t)(y0+ty+r)*C_ + x0+tx];
    __syncthreads();
    #pragma unroll
    for (int r=0;r<32;r+=8) dst[(size_t)(x0+ty+r)*C_ + y0+tx] = t[tx][ty+r];
}

// ---------------- GroupNorm ----------------
__global__ void gn_kernel(const float* __restrict__ x, const float* __restrict__ gma,
                          const float* __restrict__ bta, float* __restrict__ hn){
    const int bg = blockIdx.x;             // 64 = b*32 + g
    const int b = bg >> 5, grp = bg & 31;
    const size_t base = (size_t)b*CN + (size_t)grp*8*N_;
    const float* xp = x + base;
    float* hp = hn + base;
    const int tid = threadIdx.x;
    float s = 0.f, sq = 0.f;
    for (int i = tid; i < 8*N_; i += 256){ float v = xp[i]; s += v; sq += v*v; }
    __shared__ float ss[256], sk[256];
    ss[tid]=s; sk[tid]=sq; __syncthreads();
    for (int o=128;o>0;o>>=1){
        if (tid < o){ ss[tid]+=ss[tid+o]; sk[tid]+=sk[tid+o]; }
        __syncthreads();
    }
    const float inv = 1.0f/(8.0f*N_);
    float mu = ss[0]*inv;
    float var = sk[0]*inv - mu*mu;
    float rs = rsqrtf(var + 1e-6f);
    for (int i = tid; i < 8*N_; i += 256){
        int ch = grp*8 + (i >> 12);
        hp[i] = (xp[i]-mu)*rs*gma[ch] + bta[ch];
    }
}

// ---------------- generic TN GEMM: C[m][n] = sum_k A[k][m] * B[k][n] ----------------
// A: K x M (m contiguous, ldA), B: K x N (n contiguous, ldB), C: M x N (ldC)
// blockIdx.z = batch with strides sA/sB/sC; optional bias on M, bias on N, residual.
__global__ void __launch_bounds__(256,2) gemm_tn(
    const float* __restrict__ A, const float* __restrict__ Bm, float* __restrict__ Cp,
    int M, int N, int K, int ldA, int ldB, int ldC,
    size_t sA, size_t sB, size_t sC,
    const float* __restrict__ biasM, const float* __restrict__ biasN,
    const float* __restrict__ resid)
{
    __shared__ float As[16][128];
    __shared__ float Bs[16][128];
    const int tid = threadIdx.x;
    const int z = blockIdx.z;
    const int m0 = blockIdx.y*128, n0 = blockIdx.x*128;
    const float* Ab = A + z*sA + m0;
    const float* Bb = Bm + z*sB + n0;
    float* Cb = Cp + z*sC;
    const int ty = tid >> 4, tx = tid & 15;

    unsigned long long acc[8][4];
    #pragma unroll
    for (int i=0;i<8;i++)
        #pragma unroll
        for (int j=0;j<4;j++) acc[i][j] = 0ULL;

    for (int kk=0; kk<K; kk+=16){
        #pragma unroll
        for (int l=0;l<2;l++){
            int idx = tid + l*256;
            int k = idx >> 5, v = idx & 31;
            *(float4*)&As[k][v*4] = *(const float4*)&Ab[(size_t)(kk+k)*ldA + v*4];
            *(float4*)&Bs[k][v*4] = *(const float4*)&Bb[(size_t)(kk+k)*ldB + v*4];
        }
        __syncthreads();
        #pragma unroll
        for (int k=0;k<16;k++){
            float4 a0 = *(float4*)&As[k][ty*8];
            float4 a1 = *(float4*)&As[k][ty*8+4];
            float4 b0 = *(float4*)&Bs[k][tx*8];
            float4 b1 = *(float4*)&Bs[k][tx*8+4];
            unsigned long long bp0 = pk2(b0.x,b0.y), bp1 = pk2(b0.z,b0.w);
            unsigned long long bp2 = pk2(b1.x,b1.y), bp3 = pk2(b1.z,b1.w);
            float av[8] = {a0.x,a0.y,a0.z,a0.w,a1.x,a1.y,a1.z,a1.w};
            #pragma unroll
            for (int i=0;i<8;i++){
                unsigned long long ad = pk2(av[i],av[i]);
                fma2(acc[i][0],ad,bp0);
                fma2(acc[i][1],ad,bp1);
                fma2(acc[i][2],ad,bp2);
                fma2(acc[i][3],ad,bp3);
            }
        }
        __syncthreads();
    }
    #pragma unroll
    for (int i=0;i<8;i++){
        int m = m0 + ty*8 + i;
        float bm = biasM ? biasM[m] : 0.f;
        float c[8];
        #pragma unroll
        for (int j=0;j<4;j++){ float2 f = upk2(acc[i][j]); c[2*j]=f.x; c[2*j+1]=f.y; }
        #pragma unroll
        for (int j=0;j<8;j++){
            int n = n0 + tx*8 + j;
            float vv = c[j] + bm;
            if (biasN) vv += biasN[n];
            if (resid) vv += resid[z*sC + (size_t)m*ldC + n];
            Cb[(size_t)m*ldC + n] = vv;
        }
    }
}

// ---------------- scores: e[i][m] = exp(scale * q_i . k_m), write transposed to w_out,
//                  plus deterministic per-(i, mtile) partial row sums ----------------
__global__ void __launch_bounds__(256,2) scores_kernel(float* __restrict__ w_out)
{
    extern __shared__ float smT[];      // 128*129 floats (66048 B)
    __shared__ float As[16][128];
    __shared__ float Bs[16][128];
    const int tid = threadIdx.x;
    const int b  = blockIdx.z;
    const int i0 = blockIdx.y*128;      // attn-row tile (from q)
    const int m0 = blockIdx.x*128;      // attn-col tile (from k)
    const float* Ab = g_q + (size_t)b*CN + i0;
    const float* Bb = g_k + (size_t)b*CN + m0;
    const int ty = tid >> 4, tx = tid & 15;

    unsigned long long acc[8][4];
    #pragma unroll
    for (int i=0;i<8;i++)
        #pragma unroll
        for (int j=0;j<4;j++) acc[i][j] = 0ULL;

    for (int kk=0; kk<C_; kk+=16){
        #pragma unroll
        for (int l=0;l<2;l++){
            int idx = tid + l*256;
            int k = idx >> 5, v = idx & 31;
            *(float4*)&As[k][v*4] = *(const float4*)&Ab[(size_t)(kk+k)*N_ + v*4];
            *(float4*)&Bs[k][v*4] = *(const float4*)&Bb[(size_t)(kk+k)*N_ + v*4];
        }
        __syncthreads();
        #pragma unroll
        for (int k=0;k<16;k++){
            float4 a0 = *(float4*)&As[k][ty*8];
            float4 a1 = *(float4*)&As[k][ty*8+4];
            float4 b0 = *(float4*)&Bs[k][tx*8];
            float4 b1 = *(float4*)&Bs[k][tx*8+4];
            unsigned long long bp0 = pk2(b0.x,b0.y), bp1 = pk2(b0.z,b0.w);
            unsigned long long bp2 = pk2(b1.x,b1.y), bp3 = pk2(b1.z,b1.w);
            float av[8] = {a0.x,a0.y,a0.z,a0.w,a1.x,a1.y,a1.z,a1.w};
            #pragma unroll
            for (int i=0;i<8;i++){
                unsigned long long ad = pk2(av[i],av[i]);
                fma2(acc[i][0],ad,bp0);
                fma2(acc[i][1],ad,bp1);
                fma2(acc[i][2],ad,bp2);
                fma2(acc[i][3],ad,bp3);
            }
        }
        __syncthreads();
    }

    // exp + stage into padded smem tile: smT[i_local][m_local], pitch 129
    const float scale = 0.0625f;  // 1/sqrt(256)
    #pragma unroll
    for (int i=0;i<8;i++){
        float c[8];
        #pragma unroll
        for (int j=0;j<4;j++){ float2 f = upk2(acc[i][j]); c[2*j]=f.x; c[2*j+1]=f.y; }
        #pragma unroll
        for (int j=0;j<8;j++)
            smT[(size_t)(ty*8+i)*129 + tx*8+j] = __expf(c[j]*scale);
    }
    __syncthreads();

    // transposed, coalesced store: w_out[b][m][i] = e[i][m]
    float* wb = w_out + (size_t)b*N_*N_;
    #pragma unroll
    for (int l=0;l<16;l++){
        int idx = tid + l*256;      // 0..4095 -> (mm, iv)
        int mm = idx >> 5, iv = idx & 31;
        float4 o;
        o.x = smT[(size_t)(iv*4+0)*129 + mm];
        o.y = smT[(size_t)(iv*4+1)*129 + mm];
        o.z = smT[(size_t)(iv*4+2)*129 + mm];
        o.w = smT[(size_t)(iv*4+3)*129 + mm];
        *(float4*)&wb[(size_t)(m0+mm)*N_ + i0 + iv*4] = o;
    }

    // deterministic partial row sums over this m-tile
    if (tid < 128){
        float s = 0.f;
        #pragma unroll 8
        for (int m=0;m<128;m++) s += smT[(size_t)tid*129 + m];
        g_partial[((size_t)b*N_ + i0 + tid)*32 + blockIdx.x] = s;
    }
}

// ---------------- reduce partials -> reciprocal row sums ----------------
__global__ void rowsum_inv(){
    int idx = blockIdx.x*256 + threadIdx.x;   // 0..8191 = b*4096 + i
    float s = 0.f;
    #pragma unroll
    for (int t=0;t<32;t++) s += g_partial[(size_t)idx*32 + t];
    g_rinv[idx] = 1.0f/s;
}

// ---------------- normalize w in place: w[b][m][i] *= rinv[b][i] ----------------
__global__ void normalize_w(float* __restrict__ w_out){
    size_t idx4 = (size_t)blockIdx.x*256 + threadIdx.x;  // 8,388,608 float4s
    int b  = (int)(idx4 >> 22);
    int i4 = (int)(idx4 & 1023);
    float4 v = ((float4*)w_out)[idx4];
    float4 r = *(const float4*)&g_rinv[(b<<12) + i4*4];
    v.x *= r.x; v.y *= r.y; v.z *= r.z; v.w *= r.w;
    ((float4*)w_out)[idx4] = v;
}

// ---------------- host launch ----------------
extern "C" void kernel_launch(void* const* d_in, const int* in_sizes, int n_in,
                              void* d_out, int out_size){
    const float* x    = (const float*)d_in[0];
    const float* gma  = (const float*)d_in[1];
    const float* bta  = (const float*)d_in[2];
    const float* wq   = (const float*)d_in[3];
    const float* bq   = (const float*)d_in[4];
    const float* wk   = (const float*)d_in[5];
    const float* bk   = (const float*)d_in[6];
    const float* wv   = (const float*)d_in[7];
    const float* bv   = (const float*)d_in[8];
    const float* wp   = (const float*)d_in[9];
    const float* bp   = (const float*)d_in[10];
    float* out   = (float*)d_out;
    float* w_out = out + (size_t)B_*CN;     // attn output region (b, m, i)

    float *p_hn, *p_wT, *p_q, *p_k, *p_vT, *p_hv;
    cudaGetSymbolAddress((void**)&p_hn, g_hn);
    cudaGetSymbolAddress((void**)&p_wT, g_wT);
    cudaGetSymbolAddress((void**)&p_q,  g_q);
    cudaGetSymbolAddress((void**)&p_k,  g_k);
    cudaGetSymbolAddress((void**)&p_vT, g_vT);
    cudaGetSymbolAddress((void**)&p_hv, g_hv);

    cudaFuncSetAttribute(scores_kernel, cudaFuncAttributeMaxDynamicSharedMemorySize, 128*129*4);

    transpose4<<<dim3(8,8,4), dim3(32,8)>>>(wq, wk, wv, wp, p_wT);
    gn_kernel<<<64, 256>>>(x, gma, bta, p_hn);

    // q[o,n], k[o,n]  (M=256 channels, N=4096 spatial, K=256)
    gemm_tn<<<dim3(32,2,2), 256>>>(p_wT,           p_hn, p_q, 256, 4096, 256, 256, 4096, 4096,
                                   0, (size_t)CN, (size_t)CN, bq, nullptr, nullptr);
    gemm_tn<<<dim3(32,2,2), 256>>>(p_wT + C_*C_,   p_hn, p_k, 256, 4096, 256, 256, 4096, 4096,
                                   0, (size_t)CN, (size_t)CN, bk, nullptr, nullptr);
    // vT[n,o]  (M=4096 spatial, N=256 channels, K=256) -> transposed v for PV gemm
    gemm_tn<<<dim3(2,32,2), 256>>>(p_hn, p_wT + 2*C_*C_, p_vT, 4096, 256, 256, 4096, 256, 256,
                                   (size_t)CN, 0, (size_t)CN, nullptr, bv, nullptr);

    // e = exp(qk/16) written transposed into w_out + partial row sums
    scores_kernel<<<dim3(32,32,2), 256, 128*129*4>>>(w_out);
    rowsum_inv<<<32, 256>>>();
    normalize_w<<<32768, 256>>>(w_out);

    // hv[c,i] = sum_m vT[m,c] * attn_w[m,i]   (M=256, N=4096, K=4096)
    gemm_tn<<<dim3(32,2,2), 256>>>(p_vT, w_out, p_hv, 256, 4096, 4096, 256, 4096, 4096,
                                   (size_t)CN, (size_t)N_*N_, (size_t)CN, nullptr, nullptr, nullptr);

    // out = x + wp*hv + bp   (M=256, N=4096, K=256)
    gemm_tn<<<dim3(32,2,2), 256>>>(p_wT + 3*C_*C_, p_hv, out, 256, 4096, 256, 256, 4096, 4096,
                                   0, (size_t)CN, (size_t)CN, bp, nullptr, x);
}

// round 8
// speedup vs baseline: 1.5969x; 1.5969x over previous
#include <cuda_runtime.h>
#include <cuda_bf16.h>
#include <cstdint>
#include <cstddef>

#define B_ 2
#define C_ 256
#define N_ 4096
#define CN (C_*N_)

// ---------------- scratch (static __device__, no allocation) ----------------
__device__ float g_hn[B_*CN];          // groupnorm output (b, c, n)
__device__ float g_wT[4*C_*C_];        // wq^T, wk^T, wv^T, wp^T  (c, o)
__device__ float g_hv[B_*CN];          // hv (b, c, n)
__device__ float g_partial[B_*N_*32];  // per (b,i,mtile) partial exp-sums
__device__ float g_rinv[B_*N_];        // 1/rowsum

// bf16 hi/lo split operands for tensor-core GEMMs
__device__ __nv_bfloat16 g_qTh[B_*N_*C_], g_qTl[B_*N_*C_];   // qT (b, n, c)
__device__ __nv_bfloat16 g_kTh[B_*N_*C_], g_kTl[B_*N_*C_];   // kT (b, n, c)
__device__ __nv_bfloat16 g_vh [B_*CN],    g_vl [B_*CN];      // v  (b, c, n)
__device__ __nv_bfloat16 g_eh [(size_t)B_*N_*N_];            // e  (b, i, m) hi
__device__ __nv_bfloat16 g_el [(size_t)B_*N_*N_];            // e  (b, i, m) lo

// ---------------- packed f32x2 helpers (for the K=256 fp32 gemms) ----------------
__device__ __forceinline__ unsigned long long pk2(float lo, float hi){
    unsigned long long r;
    asm("mov.b64 %0,{%1,%2};" : "=l"(r) : "f"(lo), "f"(hi));
    return r;
}
__device__ __forceinline__ float2 upk2(unsigned long long v){
    float2 f;
    asm("mov.b64 {%0,%1},%2;" : "=f"(f.x), "=f"(f.y) : "l"(v));
    return f;
}
__device__ __forceinline__ void fma2(unsigned long long& d, unsigned long long a, unsigned long long b){
    asm("fma.rn.f32x2 %0,%1,%2,%0;" : "+l"(d) : "l"(a), "l"(b));
}

// ---------------- mma.sync helpers (baseline PTX, valid on sm_103) ----------------
__device__ __forceinline__ uint32_t smem_u32(const void* p){
    uint32_t a;
    asm("{ .reg .u64 t; cvta.to.shared.u64 t, %1; cvt.u32.u64 %0, t; }" : "=r"(a) : "l"(p));
    return a;
}
__device__ __forceinline__ uint32_t sw128(uint32_t o){ return o ^ ((o >> 3) & 0x70); }

__device__ __forceinline__ void ldsm4(uint32_t r[4], uint32_t addr){
    asm volatile("ldmatrix.sync.aligned.m8n8.x4.shared.b16 {%0,%1,%2,%3}, [%4];"
        : "=r"(r[0]), "=r"(r[1]), "=r"(r[2]), "=r"(r[3]) : "r"(addr));
}
__device__ __forceinline__ void mma16816(float d[4], const uint32_t a[4], uint32_t b0, uint32_t b1){
    asm volatile("mma.sync.aligned.m16n8k16.row.col.f32.bf16.bf16.f32 "
        "{%0,%1,%2,%3}, {%4,%5,%6,%7}, {%8,%9}, {%0,%1,%2,%3};"
        : "+f"(d[0]), "+f"(d[1]), "+f"(d[2]), "+f"(d[3])
        : "r"(a[0]), "r"(a[1]), "r"(a[2]), "r"(a[3]), "r"(b0), "r"(b1));
}

// 128x128 output tile, K in 64-wide chunks, bf16 hi/lo (3 MMAs per k16).
// A rows (m, k-major, stride), B rows (n, k-major, stride). 256 threads.
// SMEM: AH@0, AL@16K, BH@32K, BL@48K, each 128x64 bf16 SW128-swizzled.
__device__ __forceinline__ void mma_core(
    const __nv_bfloat16* __restrict__ Ah, const __nv_bfloat16* __restrict__ Al,
    const __nv_bfloat16* __restrict__ Bh, const __nv_bfloat16* __restrict__ Bl,
    int stride, int K, char* smem, uint32_t sb, float acc[2][8][4])
{
    const int tid  = threadIdx.x;
    const int lane = tid & 31, wid = tid >> 5;
    const int wm = (wid & 3) * 32, wn = (wid >> 2) * 64;
    const int lrow = ((lane >> 3) & 1) * 8 + (lane & 7);   // ldmatrix row within 16
    const int lk   = (lane >> 4) * 8;                      // ldmatrix k-half

    for (int kk = 0; kk < K; kk += 64){
        #pragma unroll
        for (int t = 0; t < 4; t++){
            int idx = tid + t*256;             // 0..1023 -> (row, 16B chunk)
            int r = idx >> 3, c16 = idx & 7;
            uint32_t so = sw128((uint32_t)(r*128 + c16*16));
            size_t go = (size_t)r*stride + kk + c16*8;
            *(uint4*)(smem + 0     + so) = *(const uint4*)(Ah + go);
            *(uint4*)(smem + 16384 + so) = *(const uint4*)(Al + go);
            *(uint4*)(smem + 32768 + so) = *(const uint4*)(Bh + go);
            *(uint4*)(smem + 49152 + so) = *(const uint4*)(Bl + go);
        }
        __syncthreads();
        #pragma unroll
        for (int k16 = 0; k16 < 4; k16++){
            uint32_t ah[2][4], al[2][4];
            #pragma unroll
            for (int mf = 0; mf < 2; mf++){
                uint32_t off = sw128((uint32_t)((wm + mf*16 + lrow)*128 + (k16*16 + lk)*2));
                ldsm4(ah[mf], sb + 0     + off);
                ldsm4(al[mf], sb + 16384 + off);
            }
            #pragma unroll
            for (int nf2 = 0; nf2 < 4; nf2++){
                uint32_t boff = sw128((uint32_t)((wn + nf2*16 + lrow)*128 + (k16*16 + lk)*2));
                uint32_t bh[4], bl[4];
                ldsm4(bh, sb + 32768 + boff);
                ldsm4(bl, sb + 49152 + boff);
                #pragma unroll
                for (int mf = 0; mf < 2; mf++){
                    #pragma unroll
                    for (int w = 0; w < 2; w++){
                        int nf = nf2*2 + w;
                        mma16816(acc[mf][nf], ah[mf], bh[w], bh[w+2]);
                        mma16816(acc[mf][nf], ah[mf], bl[w], bl[w+2]);
                        mma16816(acc[mf][nf], al[mf], bh[w], bh[w+2]);
                    }
                }
            }
        }
        __syncthreads();
    }
}

// ---------------- weight transpose: wT[c][o] = W[o][c] ----------------
__global__ void transpose4(const float* __restrict__ wq, const float* __restrict__ wk,
                           const float* __restrict__ wv, const float* __restrict__ wp,
                           float* __restrict__ wT){
    __shared__ float t[32][33];
    const float* src = (blockIdx.z==0)?wq:(blockIdx.z==1)?wk:(blockIdx.z==2)?wv:wp;
    float* dst = wT + (size_t)blockIdx.z*C_*C_;
    int x0 = blockIdx.x*32, y0 = blockIdx.y*32;
    int tx = threadIdx.x, ty = threadIdx.y;
    #pragma unroll
    for (int r=0;r<32;r+=8) t[ty+r][tx] = src[(size_t)(y0+ty+r)*C_ + x0+tx];
    __syncthreads();
    #pragma unroll
    for (int r=0;r<32;r+=8) dst[(size_t)(x0+ty+r)*C_ + y0+tx] = t[tx][ty+r];
}

// ---------------- GroupNorm ----------------
__global__ void gn_kernel(const float* __restrict__ x, const float* __restrict__ gma,
                          const float* __restrict__ bta, float* __restrict__ hn){
    const int bg = blockIdx.x;
    const int b = bg >> 5, grp = bg & 31;
    const size_t base = (size_t)b*CN + (size_t)grp*8*N_;
    const float* xp = x + base;
    float* hp = hn + base;
    const int tid = threadIdx.x;
    float s = 0.f, sq = 0.f;
    for (int i = tid; i < 8*N_; i += 256){ float v = xp[i]; s += v; sq += v*v; }
    __shared__ float ss[256], sk[256];
    ss[tid]=s; sk[tid]=sq; __syncthreads();
    for (int o=128;o>0;o>>=1){
        if (tid < o){ ss[tid]+=ss[tid+o]; sk[tid]+=sk[tid+o]; }
        __syncthreads();
    }
    const float inv = 1.0f/(8.0f*N_);
    float mu = ss[0]*inv;
    float var = sk[0]*inv - mu*mu;
    float rs = rsqrtf(var + 1e-6f);
    for (int i = tid; i < 8*N_; i += 256){
        int ch = grp*8 + (i >> 12);
        hp[i] = (xp[i]-mu)*rs*gma[ch] + bta[ch];
    }
}

// ---------------- fp32 TN GEMM (f32x2): used for the final projection ----------------
__global__ void __launch_bounds__(256,2) gemm_tn(
    const float* __restrict__ A, const float* __restrict__ Bm, float* __restrict__ Cp,
    int M, int N, int K, int ldA, int ldB, int ldC,
    size_t sA, size_t sB, size_t sC,
    const float* __restrict__ biasM, const float* __restrict__ biasN,
    const float* __restrict__ resid)
{
    __shared__ float As[16][128];
    __shared__ float Bs[16][128];
    const int tid = threadIdx.x;
    const int z = blockIdx.z;
    const int m0 = blockIdx.y*128, n0 = blockIdx.x*128;
    const float* Ab = A + z*sA + m0;
    const float* Bb = Bm + z*sB + n0;
    float* Cb = Cp + z*sC;
    const int ty = tid >> 4, tx = tid & 15;

    unsigned long long acc[8][4];
    #pragma unroll
    for (int i=0;i<8;i++)
        #pragma unroll
        for (int j=0;j<4;j++) acc[i][j] = 0ULL;

    for (int kk=0; kk<K; kk+=16){
        #pragma unroll
        for (int l=0;l<2;l++){
            int idx = tid + l*256;
            int k = idx >> 5, v = idx & 31;
            *(float4*)&As[k][v*4] = *(const float4*)&Ab[(size_t)(kk+k)*ldA + v*4];
            *(float4*)&Bs[k][v*4] = *(const float4*)&Bb[(size_t)(kk+k)*ldB + v*4];
        }
        __syncthreads();
        #pragma unroll
        for (int k=0;k<16;k++){
            float4 a0 = *(float4*)&As[k][ty*8];
            float4 a1 = *(float4*)&As[k][ty*8+4];
            float4 b0 = *(float4*)&Bs[k][tx*8];
            float4 b1 = *(float4*)&Bs[k][tx*8+4];
            unsigned long long bp0 = pk2(b0.x,b0.y), bp1 = pk2(b0.z,b0.w);
            unsigned long long bp2 = pk2(b1.x,b1.y), bp3 = pk2(b1.z,b1.w);
            float av[8] = {a0.x,a0.y,a0.z,a0.w,a1.x,a1.y,a1.z,a1.w};
            #pragma unroll
            for (int i=0;i<8;i++){
                unsigned long long ad = pk2(av[i],av[i]);
                fma2(acc[i][0],ad,bp0);
                fma2(acc[i][1],ad,bp1);
                fma2(acc[i][2],ad,bp2);
                fma2(acc[i][3],ad,bp3);
            }
        }
        __syncthreads();
    }
    #pragma unroll
    for (int i=0;i<8;i++){
        int m = m0 + ty*8 + i;
        float bm = biasM ? biasM[m] : 0.f;
        float c[8];
        #pragma unroll
        for (int j=0;j<4;j++){ float2 f = upk2(acc[i][j]); c[2*j]=f.x; c[2*j+1]=f.y; }
        #pragma unroll
        for (int j=0;j<8;j++){
            int n = n0 + tx*8 + j;
            float vv = c[j] + bm;
            if (biasN) vv += biasN[n];
            if (resid) vv += resid[z*sC + (size_t)m*ldC + n];
            Cb[(size_t)m*ldC + n] = vv;
        }
    }
}

// ---------------- fp32 TN GEMM with bf16 hi/lo split epilogue ----------------
__global__ void __launch_bounds__(256,2) gemm_tn_bf16(
    const float* __restrict__ A, const float* __restrict__ Bm,
    __nv_bfloat16* __restrict__ Ch, __nv_bfloat16* __restrict__ Cl,
    int M, int N, int K, int ldA, int ldB, int ldC,
    size_t sA, size_t sB, size_t sC,
    const float* __restrict__ biasM, const float* __restrict__ biasN)
{
    __shared__ float As[16][128];
    __shared__ float Bs[16][128];
    const int tid = threadIdx.x;
    const int z = blockIdx.z;
    const int m0 = blockIdx.y*128, n0 = blockIdx.x*128;
    const float* Ab = A + z*sA + m0;
    const float* Bb = Bm + z*sB + n0;
    const int ty = tid >> 4, tx = tid & 15;

    unsigned long long acc[8][4];
    #pragma unroll
    for (int i=0;i<8;i++)
        #pragma unroll
        for (int j=0;j<4;j++) acc[i][j] = 0ULL;

    for (int kk=0; kk<K; kk+=16){
        #pragma unroll
        for (int l=0;l<2;l++){
            int idx = tid + l*256;
            int k = idx >> 5, v = idx & 31;
            *(float4*)&As[k][v*4] = *(const float4*)&Ab[(size_t)(kk+k)*ldA + v*4];
            *(float4*)&Bs[k][v*4] = *(const float4*)&Bb[(size_t)(kk+k)*ldB + v*4];
        }
        __syncthreads();
        #pragma unroll
        for (int k=0;k<16;k++){
            float4 a0 = *(float4*)&As[k][ty*8];
            float4 a1 = *(float4*)&As[k][ty*8+4];
            float4 b0 = *(float4*)&Bs[k][tx*8];
            float4 b1 = *(float4*)&Bs[k][tx*8+4];
            unsigned long long bp0 = pk2(b0.x,b0.y), bp1 = pk2(b0.z,b0.w);
            unsigned long long bp2 = pk2(b1.x,b1.y), bp3 = pk2(b1.z,b1.w);
            float av[8] = {a0.x,a0.y,a0.z,a0.w,a1.x,a1.y,a1.z,a1.w};
            #pragma unroll
            for (int i=0;i<8;i++){
                unsigned long long ad = pk2(av[i],av[i]);
                fma2(acc[i][0],ad,bp0);
                fma2(acc[i][1],ad,bp1);
                fma2(acc[i][2],ad,bp2);
                fma2(acc[i][3],ad,bp3);
            }
        }
        __syncthreads();
    }
    #pragma unroll
    for (int i=0;i<8;i++){
        int m = m0 + ty*8 + i;
        float bm = biasM ? biasM[m] : 0.f;
        float c[8];
        #pragma unroll
        for (int j=0;j<4;j++){ float2 f = upk2(acc[i][j]); c[2*j]=f.x; c[2*j+1]=f.y; }
        size_t rowoff = z*sC + (size_t)m*ldC + n0 + tx*8;
        #pragma unroll
        for (int j=0;j<8;j+=2){
            float v0 = c[j]   + bm;
            float v1 = c[j+1] + bm;
            if (biasN){ int n = n0 + tx*8 + j; v0 += biasN[n]; v1 += biasN[n+1]; }
            __nv_bfloat16 h0 = __float2bfloat16(v0);
            __nv_bfloat16 h1 = __float2bfloat16(v1);
            __nv_bfloat16 l0 = __float2bfloat16(v0 - __bfloat162float(h0));
            __nv_bfloat16 l1 = __float2bfloat16(v1 - __bfloat162float(h1));
            *(uint32_t*)&Ch[rowoff + j] = (uint32_t)__bfloat16_as_ushort(h0) | ((uint32_t)__bfloat16_as_ushort(h1) << 16);
            *(uint32_t*)&Cl[rowoff + j] = (uint32_t)__bfloat16_as_ushort(l0) | ((uint32_t)__bfloat16_as_ushort(l1) << 16);
        }
    }
}

// ---------------- mma.sync scores: S = q . k^T, e = exp(S/16) ----------------
// grid: x = m-tile (32), y = i-tile (32), z = b; 256 threads
__global__ void __launch_bounds__(256) scores_mma(float* __restrict__ w_out)
{
    extern __shared__ char smem[];
    uint32_t sb = smem_u32(smem);
    const int tid = threadIdx.x;
    const int b  = blockIdx.z;
    const int m0 = blockIdx.x*128;      // attn-col tile (k rows)
    const int i0 = blockIdx.y*128;      // attn-row tile (q rows)

    float acc[2][8][4];
    #pragma unroll
    for (int mf=0;mf<2;mf++)
        #pragma unroll
        for (int nf=0;nf<8;nf++)
            #pragma unroll
            for (int r=0;r<4;r++) acc[mf][nf][r] = 0.f;

    mma_core(g_qTh + ((size_t)b*N_ + i0)*C_, g_qTl + ((size_t)b*N_ + i0)*C_,
             g_kTh + ((size_t)b*N_ + m0)*C_, g_kTl + ((size_t)b*N_ + m0)*C_,
             C_, C_, smem, sb, acc);

    // epilogue: exp into smT[i_local][m_local] (pitch 129)
    float* smT = (float*)smem;
    const int lane = tid & 31, wid = tid >> 5;
    const int wm = (wid & 3) * 32, wn = (wid >> 2) * 64;
    const int gid = lane >> 2, tig = lane & 3;
    #pragma unroll
    for (int mf=0;mf<2;mf++)
        #pragma unroll
        for (int nf=0;nf<8;nf++)
            #pragma unroll
            for (int h=0;h<2;h++){
                int il = wm + mf*16 + gid + h*8;
                int ml = wn + nf*8 + tig*2;
                smT[il*129 + ml]     = __expf(acc[mf][nf][h*2]   * 0.0625f);
                smT[il*129 + ml + 1] = __expf(acc[mf][nf][h*2+1] * 0.0625f);
            }
    __syncthreads();

    // transposed, coalesced store: w_out[b][m][i] = e[i][m] (unnormalized)
    float* wb = w_out + (size_t)b*N_*N_;
    #pragma unroll
    for (int l=0;l<16;l++){
        int idx = tid + l*256;          // 0..4095 -> (mm, iv)
        int mm = idx >> 5, iv = idx & 31;
        float4 o;
        o.x = smT[(iv*4+0)*129 + mm];
        o.y = smT[(iv*4+1)*129 + mm];
        o.z = smT[(iv*4+2)*129 + mm];
        o.w = smT[(iv*4+3)*129 + mm];
        *(float4*)&wb[(size_t)(m0+mm)*N_ + i0 + iv*4] = o;
    }

    // e bf16 hi/lo in (i, m): thread -> (row, half)
    {
        int il = tid >> 1, half = tid & 1;
        const float* row = smT + il*129 + half*64;
        size_t go = ((size_t)b*N_ + i0 + il)*N_ + m0 + half*64;
        #pragma unroll
        for (int cb=0; cb<64; cb+=8){
            uint32_t hb[4], lb[4];
            #pragma unroll
            for (int q=0;q<4;q++){
                float e0 = row[cb + q*2], e1 = row[cb + q*2 + 1];
                __nv_bfloat16 h0 = __float2bfloat16(e0);
                __nv_bfloat16 h1 = __float2bfloat16(e1);
                __nv_bfloat16 l0 = __float2bfloat16(e0 - __bfloat162float(h0));
                __nv_bfloat16 l1 = __float2bfloat16(e1 - __bfloat162float(h1));
                hb[q] = (uint32_t)__bfloat16_as_ushort(h0) | ((uint32_t)__bfloat16_as_ushort(h1) << 16);
                lb[q] = (uint32_t)__bfloat16_as_ushort(l0) | ((uint32_t)__bfloat16_as_ushort(l1) << 16);
            }
            *(uint4*)&g_eh[go + cb] = *(uint4*)hb;
            *(uint4*)&g_el[go + cb] = *(uint4*)lb;
        }
    }

    // deterministic partial row sums over this m-tile
    if (tid < 128){
        float s = 0.f;
        #pragma unroll 8
        for (int m=0;m<128;m++) s += smT[tid*129 + m];
        g_partial[((size_t)b*N_ + i0 + tid)*32 + blockIdx.x] = s;
    }
}

// ---------------- reduce partials -> reciprocal row sums ----------------
__global__ void rowsum_inv(){
    int idx = blockIdx.x*256 + threadIdx.x;
    float s = 0.f;
    #pragma unroll
    for (int t=0;t<32;t++) s += g_partial[(size_t)idx*32 + t];
    g_rinv[idx] = 1.0f/s;
}

// ---------------- normalize w in place: w[b][m][i] *= rinv[b][i] ----------------
__global__ void normalize_w(float* __restrict__ w_out){
    size_t idx4 = (size_t)blockIdx.x*256 + threadIdx.x;
    int b  = (int)(idx4 >> 22);
    int i4 = (int)(idx4 & 1023);
    float4 v = ((float4*)w_out)[idx4];
    float4 r = *(const float4*)&g_rinv[(b<<12) + i4*4];
    v.x *= r.x; v.y *= r.y; v.z *= r.z; v.w *= r.w;
    ((float4*)w_out)[idx4] = v;
}

// ---------------- mma.sync PV: hv[c][i] = (sum_m v[c][m] e[i][m]) * rinv[i] ----------------
// grid: x = i-tile (32), y = c-tile (2), z = b; 256 threads
__global__ void __launch_bounds__(256) pv_mma()
{
    extern __shared__ char smem[];
    uint32_t sb = smem_u32(smem);
    const int tid = threadIdx.x;
    const int b  = blockIdx.z;
    const int c0 = blockIdx.y*128;
    const int i0 = blockIdx.x*128;

    float acc[2][8][4];
    #pragma unroll
    for (int mf=0;mf<2;mf++)
        #pragma unroll
        for (int nf=0;nf<8;nf++)
            #pragma unroll
            for (int r=0;r<4;r++) acc[mf][nf][r] = 0.f;

    mma_core(g_vh + (size_t)b*CN + (size_t)c0*N_, g_vl + (size_t)b*CN + (size_t)c0*N_,
             g_eh + ((size_t)b*N_ + i0)*N_,       g_el + ((size_t)b*N_ + i0)*N_,
             N_, N_, smem, sb, acc);

    const float* rinv = g_rinv + (size_t)b*N_ + i0;
    const int lane = tid & 31, wid = tid >> 5;
    const int wm = (wid & 3) * 32, wn = (wid >> 2) * 64;
    const int gid = lane >> 2, tig = lane & 3;
    #pragma unroll
    for (int mf=0;mf<2;mf++)
        #pragma unroll
        for (int nf=0;nf<8;nf++)
            #pragma unroll
            for (int h=0;h<2;h++){
                int c = c0 + wm + mf*16 + gid + h*8;
                int n = wn + nf*8 + tig*2;
                float2 st;
                st.x = acc[mf][nf][h*2]   * rinv[n];
                st.y = acc[mf][nf][h*2+1] * rinv[n+1];
                *(float2*)&g_hv[(size_t)b*CN + (size_t)c*N_ + i0 + n] = st;
            }
}

#define SCORES_SMEM (128*129*4)   // 66048 (epilogue smT overlaps the 64KB tiles)
#define PV_SMEM     (65536)

// ---------------- host launch ----------------
extern "C" void kernel_launch(void* const* d_in, const int* in_sizes, int n_in,
                              void* d_out, int out_size){
    const float* x    = (const float*)d_in[0];
    const float* gma  = (const float*)d_in[1];
    const float* bta  = (const float*)d_in[2];
    const float* wq   = (const float*)d_in[3];
    const float* bq   = (const float*)d_in[4];
    const float* wk   = (const float*)d_in[5];
    const float* bk   = (const float*)d_in[6];
    const float* wv   = (const float*)d_in[7];
    const float* bv   = (const float*)d_in[8];
    const float* wp   = (const float*)d_in[9];
    const float* bp   = (const float*)d_in[10];
    float* out   = (float*)d_out;
    float* w_out = out + (size_t)B_*CN;

    float *p_hn, *p_wT, *p_hv;
    __nv_bfloat16 *p_qTh, *p_qTl, *p_kTh, *p_kTl, *p_vh, *p_vl;
    cudaGetSymbolAddress((void**)&p_hn,  g_hn);
    cudaGetSymbolAddress((void**)&p_wT,  g_wT);
    cudaGetSymbolAddress((void**)&p_hv,  g_hv);
    cudaGetSymbolAddress((void**)&p_qTh, g_qTh);
    cudaGetSymbolAddress((void**)&p_qTl, g_qTl);
    cudaGetSymbolAddress((void**)&p_kTh, g_kTh);
    cudaGetSymbolAddress((void**)&p_kTl, g_kTl);
    cudaGetSymbolAddress((void**)&p_vh,  g_vh);
    cudaGetSymbolAddress((void**)&p_vl,  g_vl);

    cudaFuncSetAttribute(scores_mma, cudaFuncAttributeMaxDynamicSharedMemorySize, SCORES_SMEM);
    cudaFuncSetAttribute(pv_mma,     cudaFuncAttributeMaxDynamicSharedMemorySize, PV_SMEM);

    transpose4<<<dim3(8,8,4), dim3(32,8)>>>(wq, wk, wv, wp, p_wT);
    gn_kernel<<<64, 256>>>(x, gma, bta, p_hn);

    // qT (b, n, c) bf16 hi/lo:  C[m=n][n=c] = sum_k hn[k][m] * wqT[k][c] + bq[c]
    gemm_tn_bf16<<<dim3(2,32,2), 256>>>(p_hn, p_wT,          p_qTh, p_qTl,
                                        4096, 256, 256, 4096, 256, 256,
                                        (size_t)CN, 0, (size_t)CN, nullptr, bq);
    gemm_tn_bf16<<<dim3(2,32,2), 256>>>(p_hn, p_wT + C_*C_,  p_kTh, p_kTl,
                                        4096, 256, 256, 4096, 256, 256,
                                        (size_t)CN, 0, (size_t)CN, nullptr, bk);
    // v (b, c, n) bf16 hi/lo:  C[m=c][n] = sum_k wvT[k][c] * hn[k][n] + bv[c]
    gemm_tn_bf16<<<dim3(32,2,2), 256>>>(p_wT + 2*C_*C_, p_hn, p_vh, p_vl,
                                        256, 4096, 256, 256, 4096, 4096,
                                        0, (size_t)CN, (size_t)CN, bv, nullptr);

    // e = exp(qk/16): unnormalized, transposed into w_out + bf16 hi/lo (i,m) + partials
    scores_mma<<<dim3(32,32,2), 256, SCORES_SMEM>>>(w_out);
    rowsum_inv<<<32, 256>>>();
    normalize_w<<<32768, 256>>>(w_out);

    // hv[c][i] = (sum_m v[c][m] e[i][m]) * rinv[i]
    pv_mma<<<dim3(32,2,2), 256, PV_SMEM>>>();

    // out = x + wp*hv + bp
    gemm_tn<<<dim3(32,2,2), 256>>>(p_wT + 3*C_*C_, p_hv, out, 256, 4096, 256, 256, 4096, 4096,
                                   0, (size_t)CN, (size_t)CN, bp, nullptr, x);
}

// round 10
// speedup vs baseline: 2.1185x; 1.3266x over previous
#include <cuda_runtime.h>
#include <cuda_bf16.h>
#include <cstdint>
#include <cstddef>

#define B_ 2
#define C_ 256
#define N_ 4096
#define CN (C_*N_)

// ---------------- scratch (static __device__, no allocation) ----------------
__device__ float g_wpT[C_*C_];         // wp^T (c, o) f32 for proj
__device__ float g_hv[B_*CN];          // hv (b, c, n) f32
__device__ float g_partial[B_*N_*32];  // per (b,i,mtile) partial exp-sums
__device__ float g_rinv[B_*N_];        // 1/rowsum

// bf16 hi/lo split operands
__device__ __nv_bfloat16 g_hnTh[B_*N_*C_], g_hnTl[B_*N_*C_]; // hn^T (b, n, c)
__device__ __nv_bfloat16 g_w3h[3*C_*C_],   g_w3l[3*C_*C_];   // wq, wk, wv (o, c)
__device__ __nv_bfloat16 g_qTh[B_*N_*C_],  g_qTl[B_*N_*C_];  // qT (b, n, c)
__device__ __nv_bfloat16 g_kTh[B_*N_*C_],  g_kTl[B_*N_*C_];  // kT (b, n, c)
__device__ __nv_bfloat16 g_vh [B_*CN],     g_vl [B_*CN];     // v  (b, c, n)
__device__ __nv_bfloat16 g_eh [(size_t)B_*N_*N_];            // e  (b, i, m) hi
__device__ __nv_bfloat16 g_el [(size_t)B_*N_*N_];            // e  (b, i, m) lo

// ---------------- packed f32x2 helpers (proj gemm) ----------------
__device__ __forceinline__ unsigned long long pk2(float lo, float hi){
    unsigned long long r;
    asm("mov.b64 %0,{%1,%2};" : "=l"(r) : "f"(lo), "f"(hi));
    return r;
}
__device__ __forceinline__ float2 upk2(unsigned long long v){
    float2 f;
    asm("mov.b64 {%0,%1},%2;" : "=f"(f.x), "=f"(f.y) : "l"(v));
    return f;
}
__device__ __forceinline__ void fma2(unsigned long long& d, unsigned long long a, unsigned long long b){
    asm("fma.rn.f32x2 %0,%1,%2,%0;" : "+l"(d) : "l"(a), "l"(b));
}

// ---------------- mma.sync helpers (baseline PTX, valid on sm_103) ----------------
__device__ __forceinline__ uint32_t smem_u32(const void* p){
    uint32_t a;
    asm("{ .reg .u64 t; cvta.to.shared.u64 t, %1; cvt.u32.u64 %0, t; }" : "=r"(a) : "l"(p));
    return a;
}
__device__ __forceinline__ uint32_t sw128(uint32_t o){ return o ^ ((o >> 3) & 0x70); }

__device__ __forceinline__ void ldsm4(uint32_t r[4], uint32_t addr){
    asm volatile("ldmatrix.sync.aligned.m8n8.x4.shared.b16 {%0,%1,%2,%3}, [%4];"
        : "=r"(r[0]), "=r"(r[1]), "=r"(r[2]), "=r"(r[3]) : "r"(addr));
}
__device__ __forceinline__ void mma16816(float d[4], const uint32_t a[4], uint32_t b0, uint32_t b1){
    asm volatile("mma.sync.aligned.m16n8k16.row.col.f32.bf16.bf16.f32 "
        "{%0,%1,%2,%3}, {%4,%5,%6,%7}, {%8,%9}, {%0,%1,%2,%3};"
        : "+f"(d[0]), "+f"(d[1]), "+f"(d[2]), "+f"(d[3])
        : "r"(a[0]), "r"(a[1]), "r"(a[2]), "r"(a[3]), "r"(b0), "r"(b1));
}
__device__ __forceinline__ void cpa16(uint32_t dst, const void* src){
    asm volatile("cp.async.cg.shared.global [%0], [%1], 16;"
        :: "r"(dst), "l"(__cvta_generic_to_global(src)) : "memory");
}
#define CP_COMMIT() asm volatile("cp.async.commit_group;" ::: "memory")
#define CP_WAIT1()  asm volatile("cp.async.wait_group 1;" ::: "memory")
#define CP_WAIT0()  asm volatile("cp.async.wait_group 0;" ::: "memory")

__device__ __forceinline__ void bfsplit2(float v0, float v1, uint32_t& hi, uint32_t& lo){
    __nv_bfloat16 h0 = __float2bfloat16(v0);
    __nv_bfloat16 h1 = __float2bfloat16(v1);
    __nv_bfloat16 l0 = __float2bfloat16(v0 - __bfloat162float(h0));
    __nv_bfloat16 l1 = __float2bfloat16(v1 - __bfloat162float(h1));
    hi = (uint32_t)__bfloat16_as_ushort(h0) | ((uint32_t)__bfloat16_as_ushort(h1) << 16);
    lo = (uint32_t)__bfloat16_as_ushort(l0) | ((uint32_t)__bfloat16_as_ushort(l1) << 16);
}

// ---------------- double-buffered 128x128 mma core ----------------
// K chunks of 64, bf16 hi/lo (3 MMAs per k16). A rows (m), B rows (n), both k-major.
// SMEM: 2 buffers x 64KB: AH@0, AL@16K, BH@32K, BL@48K, each 128x64 bf16 SW128.
__device__ __forceinline__ void mc_load(
    const __nv_bfloat16* __restrict__ Ah, const __nv_bfloat16* __restrict__ Al,
    const __nv_bfloat16* __restrict__ Bh, const __nv_bfloat16* __restrict__ Bl,
    int stride, int kk, uint32_t sbuf)
{
    const int tid = threadIdx.x;
    #pragma unroll
    for (int t = 0; t < 4; t++){
        int idx = tid + t*256;
        int r = idx >> 3, c16 = idx & 7;
        uint32_t so = sw128((uint32_t)(r*128 + c16*16));
        size_t go = (size_t)r*stride + kk + c16*8;
        cpa16(sbuf + 0     + so, Ah + go);
        cpa16(sbuf + 16384 + so, Al + go);
        cpa16(sbuf + 32768 + so, Bh + go);
        cpa16(sbuf + 49152 + so, Bl + go);
    }
}

__device__ __forceinline__ void mc_compute(uint32_t sbuf, float acc[2][8][4])
{
    const int tid  = threadIdx.x;
    const int lane = tid & 31, wid = tid >> 5;
    const int wm = (wid & 3) * 32, wn = (wid >> 2) * 64;
    const int lrow = ((lane >> 3) & 1) * 8 + (lane & 7);
    const int lk   = (lane >> 4) * 8;
    #pragma unroll
    for (int k16 = 0; k16 < 4; k16++){
        uint32_t ah[2][4], al[2][4];
        #pragma unroll
        for (int mf = 0; mf < 2; mf++){
            uint32_t off = sw128((uint32_t)((wm + mf*16 + lrow)*128 + (k16*16 + lk)*2));
            ldsm4(ah[mf], sbuf + 0     + off);
            ldsm4(al[mf], sbuf + 16384 + off);
        }
        #pragma unroll
        for (int nf2 = 0; nf2 < 4; nf2++){
            uint32_t boff = sw128((uint32_t)((wn + nf2*16 + lrow)*128 + (k16*16 + lk)*2));
            uint32_t bh[4], bl[4];
            ldsm4(bh, sbuf + 32768 + boff);
            ldsm4(bl, sbuf + 49152 + boff);
            #pragma unroll
            for (int mf = 0; mf < 2; mf++){
                #pragma unroll
                for (int w = 0; w < 2; w++){
                    int nf = nf2*2 + w;
                    mma16816(acc[mf][nf], ah[mf], bh[w], bh[w+2]);
                    mma16816(acc[mf][nf], ah[mf], bl[w], bl[w+2]);
                    mma16816(acc[mf][nf], al[mf], bh[w], bh[w+2]);
                }
            }
        }
    }
}

__device__ __forceinline__ void mma_core(
    const __nv_bfloat16* __restrict__ Ah, const __nv_bfloat16* __restrict__ Al,
    const __nv_bfloat16* __restrict__ Bh, const __nv_bfloat16* __restrict__ Bl,
    int stride, int K, uint32_t sb, float acc[2][8][4])
{
    const int nch = K >> 6;
    mc_load(Ah, Al, Bh, Bl, stride, 0, sb);
    CP_COMMIT();
    for (int c = 0; c < nch; c++){
        if (c + 1 < nch){
            mc_load(Ah, Al, Bh, Bl, stride, (c+1)*64, sb + ((c+1)&1)*65536);
            CP_COMMIT();
            CP_WAIT1();
        } else {
            CP_WAIT0();
        }
        __syncthreads();
        mc_compute(sb + (c&1)*65536, acc);
        __syncthreads();
    }
}

#define MMA_SMEM 131072

// ---------------- wp transpose (f32, for proj) ----------------
__global__ void transpose_wp(const float* __restrict__ wp, float* __restrict__ wT){
    __shared__ float t[32][33];
    int x0 = blockIdx.x*32, y0 = blockIdx.y*32;
    int tx = threadIdx.x, ty = threadIdx.y;
    #pragma unroll
    for (int r=0;r<32;r+=8) t[ty+r][tx] = wp[(size_t)(y0+ty+r)*C_ + x0+tx];
    __syncthreads();
    #pragma unroll
    for (int r=0;r<32;r+=8) wT[(size_t)(x0+ty+r)*C_ + y0+tx] = t[tx][ty+r];
}

// ---------------- wq/wk/wv -> bf16 hi/lo (layout unchanged: (o, c) k-major) ----------------
__global__ void conv_w3(const float* __restrict__ wq, const float* __restrict__ wk,
                        const float* __restrict__ wv){
    int idx = blockIdx.x*256 + threadIdx.x;       // 0 .. 3*65536-1, x2 elems
    int which = idx >> 15;                        // 65536/2 = 32768 pairs per weight
    int pair  = idx & 32767;
    const float* src = (which==0)?wq:(which==1)?wk:wv;
    float v0 = src[pair*2], v1 = src[pair*2+1];
    uint32_t hi, lo;
    bfsplit2(v0, v1, hi, lo);
    *(uint32_t*)&g_w3h[(size_t)which*C_*C_ + pair*2] = hi;
    *(uint32_t*)&g_w3l[(size_t)which*C_*C_ + pair*2] = lo;
}

// ---------------- GroupNorm -> hn^T (b, n, c) bf16 hi/lo ----------------
__global__ void gn_kernel(const float* __restrict__ x, const float* __restrict__ gma,
                          const float* __restrict__ bta){
    const int bg = blockIdx.x;                 // 64 = b*32 + grp
    const int b = bg >> 5, grp = bg & 31;
    const size_t base = (size_t)b*CN + (size_t)grp*8*N_;
    const float* xp = x + base;
    const int tid = threadIdx.x;
    float s = 0.f, sq = 0.f;
    for (int i = tid; i < 8*N_; i += 256){ float v = xp[i]; s += v; sq += v*v; }
    __shared__ float ss[256], sk[256];
    ss[tid]=s; sk[tid]=sq; __syncthreads();
    for (int o=128;o>0;o>>=1){
        if (tid < o){ ss[tid]+=ss[tid+o]; sk[tid]+=sk[tid+o]; }
        __syncthreads();
    }
    const float inv = 1.0f/(8.0f*N_);
    float mu = ss[0]*inv;
    float var = sk[0]*inv - mu*mu;
    float rs = rsqrtf(var + 1e-6f);
    float gm[8], bt[8];
    #pragma unroll
    for (int ch=0; ch<8; ch++){ gm[ch] = gma[grp*8+ch]*rs; bt[ch] = bta[grp*8+ch]; }
    for (int n = tid; n < N_; n += 256){
        uint32_t hi[4], lo[4];
        #pragma unroll
        for (int p=0; p<4; p++){
            float v0 = (xp[(size_t)(p*2  )*N_ + n] - mu)*gm[p*2]   + bt[p*2];
            float v1 = (xp[(size_t)(p*2+1)*N_ + n] - mu)*gm[p*2+1] + bt[p*2+1];
            bfsplit2(v0, v1, hi[p], lo[p]);
        }
        size_t off = ((size_t)b*N_ + n)*C_ + grp*8;
        *(uint4*)&g_hnTh[off] = *(uint4*)hi;
        *(uint4*)&g_hnTl[off] = *(uint4*)lo;
    }
}

// ---------------- QKV via mma.sync: C[m][n] = sum_k A[m][k] B[n][k] + bias ----------------
// grid (nTiles, mTiles, b); 256 threads
__global__ void __launch_bounds__(256) qkv_mma(
    const __nv_bfloat16* __restrict__ Ah, const __nv_bfloat16* __restrict__ Al, size_t sAb,
    const __nv_bfloat16* __restrict__ Bh, const __nv_bfloat16* __restrict__ Bl, size_t sBb,
    __nv_bfloat16* __restrict__ Ch, __nv_bfloat16* __restrict__ Cl, int ldC, size_t sCb,
    const float* __restrict__ bias, int biasRow)
{
    extern __shared__ char smem[];
    uint32_t sb = smem_u32(smem);
    const int b = blockIdx.z;
    const int m0 = blockIdx.y*128, n0 = blockIdx.x*128;

    float acc[2][8][4];
    #pragma unroll
    for (int mf=0;mf<2;mf++)
        #pragma unroll
        for (int nf=0;nf<8;nf++)
            #pragma unroll
            for (int r=0;r<4;r++) acc[mf][nf][r] = 0.f;

    mma_core(Ah + b*sAb + (size_t)m0*C_, Al + b*sAb + (size_t)m0*C_,
             Bh + b*sBb + (size_t)n0*C_, Bl + b*sBb + (size_t)n0*C_,
             C_, C_, sb, acc);

    const int tid = threadIdx.x, lane = tid & 31, wid = tid >> 5;
    const int wm = (wid & 3) * 32, wn = (wid >> 2) * 64;
    const int gid = lane >> 2, tig = lane & 3;
    #pragma unroll
    for (int mf=0;mf<2;mf++)
        #pragma unroll
        for (int nf=0;nf<8;nf++)
            #pragma unroll
            for (int h=0;h<2;h++){
                int m = m0 + wm + mf*16 + gid + h*8;
                int n = n0 + wn + nf*8 + tig*2;
                float v0 = acc[mf][nf][h*2], v1 = acc[mf][nf][h*2+1];
                if (biasRow){ float bm = bias[m]; v0 += bm; v1 += bm; }
                else        { v0 += bias[n]; v1 += bias[n+1]; }
                uint32_t hi, lo;
                bfsplit2(v0, v1, hi, lo);
                size_t off = b*sCb + (size_t)m*ldC + n;
                *(uint32_t*)&Ch[off] = hi;
                *(uint32_t*)&Cl[off] = lo;
            }
}

// ---------------- scores: S = q.k^T, e = exp(S/16) ----------------
// grid: x = m-tile (32), y = i-tile (32), z = b; 256 threads
__global__ void __launch_bounds__(256) scores_mma(float* __restrict__ w_out)
{
    extern __shared__ char smem[];
    uint32_t sb = smem_u32(smem);
    const int tid = threadIdx.x;
    const int b  = blockIdx.z;
    const int m0 = blockIdx.x*128;
    const int i0 = blockIdx.y*128;

    float acc[2][8][4];
    #pragma unroll
    for (int mf=0;mf<2;mf++)
        #pragma unroll
        for (int nf=0;nf<8;nf++)
            #pragma unroll
            for (int r=0;r<4;r++) acc[mf][nf][r] = 0.f;

    mma_core(g_qTh + ((size_t)b*N_ + i0)*C_, g_qTl + ((size_t)b*N_ + i0)*C_,
             g_kTh + ((size_t)b*N_ + m0)*C_, g_kTl + ((size_t)b*N_ + m0)*C_,
             C_, C_, sb, acc);

    // epilogue: exp into smT[i_local][m_local] (pitch 129)
    float* smT = (float*)smem;
    const int lane = tid & 31, wid = tid >> 5;
    const int wm = (wid & 3) * 32, wn = (wid >> 2) * 64;
    const int gid = lane >> 2, tig = lane & 3;
    #pragma unroll
    for (int mf=0;mf<2;mf++)
        #pragma unroll
        for (int nf=0;nf<8;nf++)
            #pragma unroll
            for (int h=0;h<2;h++){
                int il = wm + mf*16 + gid + h*8;
                int ml = wn + nf*8 + tig*2;
                smT[il*129 + ml]     = __expf(acc[mf][nf][h*2]   * 0.0625f);
                smT[il*129 + ml + 1] = __expf(acc[mf][nf][h*2+1] * 0.0625f);
            }
    __syncthreads();

    // transposed, coalesced store: w_out[b][m][i] = e[i][m] (unnormalized)
    float* wb = w_out + (size_t)b*N_*N_;
    #pragma unroll
    for (int l=0;l<16;l++){
        int idx = tid + l*256;
        int mm = idx >> 5, iv = idx & 31;
        float4 o;
        o.x = smT[(iv*4+0)*129 + mm];
        o.y = smT[(iv*4+1)*129 + mm];
        o.z = smT[(iv*4+2)*129 + mm];
        o.w = smT[(iv*4+3)*129 + mm];
        *(float4*)&wb[(size_t)(m0+mm)*N_ + i0 + iv*4] = o;
    }

    // e bf16 hi/lo in (i, m)
    {
        int il = tid >> 1, half = tid & 1;
        const float* row = smT + il*129 + half*64;
        size_t go = ((size_t)b*N_ + i0 + il)*N_ + m0 + half*64;
        #pragma unroll
        for (int cb=0; cb<64; cb+=8){
            uint32_t hb[4], lb[4];
            #pragma unroll
            for (int q=0;q<4;q++)
                bfsplit2(row[cb+q*2], row[cb+q*2+1], hb[q], lb[q]);
            *(uint4*)&g_eh[go + cb] = *(uint4*)hb;
            *(uint4*)&g_el[go + cb] = *(uint4*)lb;
        }
    }

    // deterministic partial row sums over this m-tile
    if (tid < 128){
        float s = 0.f;
        #pragma unroll 8
        for (int m=0;m<128;m++) s += smT[tid*129 + m];
        g_partial[((size_t)b*N_ + i0 + tid)*32 + blockIdx.x] = s;
    }
}

// ---------------- reduce partials -> reciprocal row sums ----------------
__global__ void rowsum_inv(){
    int idx = blockIdx.x*256 + threadIdx.x;
    float s = 0.f;
    #pragma unroll
    for (int t=0;t<32;t++) s += g_partial[(size_t)idx*32 + t];
    g_rinv[idx] = 1.0f/s;
}

// ---------------- normalize w in place: w[b][m][i] *= rinv[b][i] ----------------
__global__ void normalize_w(float* __restrict__ w_out){
    size_t idx4 = (size_t)blockIdx.x*256 + threadIdx.x;
    int b  = (int)(idx4 >> 22);
    int i4 = (int)(idx4 & 1023);
    float4 v = ((float4*)w_out)[idx4];
    float4 r = *(const float4*)&g_rinv[(b<<12) + i4*4];
    v.x *= r.x; v.y *= r.y; v.z *= r.z; v.w *= r.w;
    ((float4*)w_out)[idx4] = v;
}

// ---------------- PV: hv[c][i] = (sum_m v[c][m] e[i][m]) * rinv[i] ----------------
// grid: x = i-tile (32), y = c-tile (2), z = b; 256 threads
__global__ void __launch_bounds__(256) pv_mma()
{
    extern __shared__ char smem[];
    uint32_t sb = smem_u32(smem);
    const int tid = threadIdx.x;
    const int b  = blockIdx.z;
    const int c0 = blockIdx.y*128;
    const int i0 = blockIdx.x*128;

    float acc[2][8][4];
    #pragma unroll
    for (int mf=0;mf<2;mf++)
        #pragma unroll
        for (int nf=0;nf<8;nf++)
            #pragma unroll
            for (int r=0;r<4;r++) acc[mf][nf][r] = 0.f;

    mma_core(g_vh + (size_t)b*CN + (size_t)c0*N_, g_vl + (size_t)b*CN + (size_t)c0*N_,
             g_eh + ((size_t)b*N_ + i0)*N_,       g_el + ((size_t)b*N_ + i0)*N_,
             N_, N_, sb, acc);

    const float* rinv = g_rinv + (size_t)b*N_ + i0;
    const int lane = tid & 31, wid = tid >> 5;
    const int wm = (wid & 3) * 32, wn = (wid >> 2) * 64;
    const int gid = lane >> 2, tig = lane & 3;
    #pragma unroll
    for (int mf=0;mf<2;mf++)
        #pragma unroll
        for (int nf=0;nf<8;nf++)
            #pragma unroll
            for (int h=0;h<2;h++){
                int c = c0 + wm + mf*16 + gid + h*8;
                int n = wn + nf*8 + tig*2;
                float2 st;
                st.x = acc[mf][nf][h*2]   * rinv[n];
                st.y = acc[mf][nf][h*2+1] * rinv[n+1];
                *(float2*)&g_hv[(size_t)b*CN + (size_t)c*N_ + i0 + n] = st;
            }
}

// ---------------- fp32 TN GEMM (f32x2): final projection ----------------
__global__ void __launch_bounds__(256,2) gemm_tn(
    const float* __restrict__ A, const float* __restrict__ Bm, float* __restrict__ Cp,
    int ldA, int ldB, int ldC, size_t sB, size_t sC,
    const float* __restrict__ biasM, const float* __restrict__ resid)
{
    __shared__ float As[16][128];
    __shared__ float Bs[16][128];
    const int tid = threadIdx.x;
    const int z = blockIdx.z;
    const int m0 = blockIdx.y*128, n0 = blockIdx.x*128;
    const float* Ab = A + m0;
    const float* Bb = Bm + z*sB + n0;
    float* Cb = Cp + z*sC;
    const int ty = tid >> 4, tx = tid & 15;

    unsigned long long acc[8][4];
    #pragma unroll
    for (int i=0;i<8;i++)
        #pragma unroll
        for (int j=0;j<4;j++) acc[i][j] = 0ULL;

    for (int kk=0; kk<C_; kk+=16){
        #pragma unroll
        for (int l=0;l<2;l++){
            int idx = tid + l*256;
            int k = idx >> 5, v = idx & 31;
            *(float4*)&As[k][v*4] = *(const float4*)&Ab[(size_t)(kk+k)*ldA + v*4];
            *(float4*)&Bs[k][v*4] = *(const float4*)&Bb[(size_t)(kk+k)*ldB + v*4];
        }
        __syncthreads();
        #pragma unroll
        for (int k=0;k<16;k++){
            float4 a0 = *(float4*)&As[k][ty*8];
            float4 a1 = *(float4*)&As[k][ty*8+4];
            float4 b0 = *(float4*)&Bs[k][tx*8];
            float4 b1 = *(float4*)&Bs[k][tx*8+4];
            unsigned long long bp0 = pk2(b0.x,b0.y), bp1 = pk2(b0.z,b0.w);
            unsigned long long bp2 = pk2(b1.x,b1.y), bp3 = pk2(b1.z,b1.w);
            float av[8] = {a0.x,a0.y,a0.z,a0.w,a1.x,a1.y,a1.z,a1.w};
            #pragma unroll
            for (int i=0;i<8;i++){
                unsigned long long ad = pk2(av[i],av[i]);
                fma2(acc[i][0],ad,bp0);
                fma2(acc[i][1],ad,bp1);
                fma2(acc[i][2],ad,bp2);
                fma2(acc[i][3],ad,bp3);
            }
        }
        __syncthreads();
    }
    #pragma unroll
    for (int i=0;i<8;i++){
        int m = m0 + ty*8 + i;
        float bm = biasM[m];
        float c[8];
        #pragma unroll
        for (int j=0;j<4;j++){ float2 f = upk2(acc[i][j]); c[2*j]=f.x; c[2*j+1]=f.y; }
        #pragma unroll
        for (int j=0;j<8;j++){
            int n = n0 + tx*8 + j;
            Cb[(size_t)m*ldC + n] = c[j] + bm + resid[z*sC + (size_t)m*ldC + n];
        }
    }
}

// ---------------- host launch ----------------
extern "C" void kernel_launch(void* const* d_in, const int* in_sizes, int n_in,
                              void* d_out, int out_size){
    const float* x    = (const float*)d_in[0];
    const float* gma  = (const float*)d_in[1];
    const float* bta  = (const float*)d_in[2];
    const float* wq   = (const float*)d_in[3];
    const float* bq   = (const float*)d_in[4];
    const float* wk   = (const float*)d_in[5];
    const float* bk   = (const float*)d_in[6];
    const float* wv   = (const float*)d_in[7];
    const float* bv   = (const float*)d_in[8];
    const float* wp   = (const float*)d_in[9];
    const float* bp   = (const float*)d_in[10];
    float* out   = (float*)d_out;
    float* w_out = out + (size_t)B_*CN;

    float *p_wpT, *p_hv;
    __nv_bfloat16 *p_hnTh, *p_hnTl, *p_w3h, *p_w3l;
    __nv_bfloat16 *p_qTh, *p_qTl, *p_kTh, *p_kTl, *p_vh, *p_vl;
    cudaGetSymbolAddress((void**)&p_wpT,  g_wpT);
    cudaGetSymbolAddress((void**)&p_hv,   g_hv);
    cudaGetSymbolAddress((void**)&p_hnTh, g_hnTh);
    cudaGetSymbolAddress((void**)&p_hnTl, g_hnTl);
    cudaGetSymbolAddress((void**)&p_w3h,  g_w3h);
    cudaGetSymbolAddress((void**)&p_w3l,  g_w3l);
    cudaGetSymbolAddress((void**)&p_qTh,  g_qTh);
    cudaGetSymbolAddress((void**)&p_qTl,  g_qTl);
    cudaGetSymbolAddress((void**)&p_kTh,  g_kTh);
    cudaGetSymbolAddress((void**)&p_kTl,  g_kTl);
    cudaGetSymbolAddress((void**)&p_vh,   g_vh);
    cudaGetSymbolAddress((void**)&p_vl,   g_vl);

    cudaFuncSetAttribute(qkv_mma,    cudaFuncAttributeMaxDynamicSharedMemorySize, MMA_SMEM);
    cudaFuncSetAttribute(scores_mma, cudaFuncAttributeMaxDynamicSharedMemorySize, MMA_SMEM);
    cudaFuncSetAttribute(pv_mma,     cudaFuncAttributeMaxDynamicSharedMemorySize, MMA_SMEM);

    conv_w3<<<384, 256>>>(wq, wk, wv);              // 3*32768 pairs
    transpose_wp<<<dim3(8,8), dim3(32,8)>>>(wp, p_wpT);
    gn_kernel<<<64, 256>>>(x, gma, bta);

    // qT[n][o] = sum_c hnT[n][c] wq[o][c] + bq[o]   (A=hnT rows n, B=wq rows o)
    qkv_mma<<<dim3(2,32,2), 256, MMA_SMEM>>>(
        p_hnTh, p_hnTl, (size_t)N_*C_,
        p_w3h,  p_w3l,  0,
        p_qTh, p_qTl, C_, (size_t)N_*C_, bq, 0);
    qkv_mma<<<dim3(2,32,2), 256, MMA_SMEM>>>(
        p_hnTh, p_hnTl, (size_t)N_*C_,
        p_w3h + C_*C_, p_w3l + C_*C_, 0,
        p_kTh, p_kTl, C_, (size_t)N_*C_, bk, 0);
    // v[o][n] = sum_c wv[o][c] hnT[n][c] + bv[o]    (A=wv rows o, B=hnT rows n)
    qkv_mma<<<dim3(32,2,2), 256, MMA_SMEM>>>(
        p_w3h + 2*C_*C_, p_w3l + 2*C_*C_, 0,
        p_hnTh, p_hnTl, (size_t)N_*C_,
        p_vh, p_vl, N_, (size_t)CN, bv, 1);

    // e = exp(qk/16): unnormalized transposed into w_out + bf16 hi/lo (i,m) + partials
    scores_mma<<<dim3(32,32,2), 256, MMA_SMEM>>>(w_out);
    rowsum_inv<<<32, 256>>>();
    normalize_w<<<32768, 256>>>(w_out);

    // hv[c][i] = (sum_m v[c][m] e[i][m]) * rinv[i]
    pv_mma<<<dim3(32,2,2), 256, MMA_SMEM>>>();

    // out = x + wpT^T hv + bp
    gemm_tn<<<dim3(32,2,2), 256>>>(p_wpT, p_hv, out, C_, N_, N_,
                                   (size_t)CN, (size_t)CN, bp, x);
}